// round 1
// baseline (speedup 1.0000x reference)
#include <cuda_runtime.h>

// Problem shape (fixed by setup_inputs)
static const int BATCH = 8;
static const int TQ    = 2048;
static const int TK    = 2048;
static const int DIM   = 1024;

// 128 MiB scratch for energy / probabilities [B, Tq, Tk]
__device__ float g_energy[(size_t)8 * 2048 * 2048];

#define BM 128
#define BN 128
#define BK 16
#define TM 8
#define TN 8
#define NTHREADS 256

// ---------------------------------------------------------------------------
// C[M,N] = A[M,K] * B[N,K]^T   (A, B row-major with inner dim K; "NT" gemm)
// grid: (N/BN, M/BM, batch)
// ---------------------------------------------------------------------------
__global__ __launch_bounds__(NTHREADS) void sgemm_nt_kernel(
    const float* __restrict__ A, const float* __restrict__ Bm, float* __restrict__ C,
    int M, int N, int K)
{
    const float* Ab = A  + (size_t)blockIdx.z * M * K;
    const float* Bb = Bm + (size_t)blockIdx.z * N * K;
    float*       Cb = C  + (size_t)blockIdx.z * M * N;

    __shared__ float As[BK][BM];
    __shared__ float Bs[BK][BN];

    const int tid = threadIdx.x;
    const int ty  = tid / (BN / TN);   // 0..15
    const int tx  = tid % (BN / TN);   // 0..15

    const int row0 = blockIdx.y * BM;
    const int col0 = blockIdx.x * BN;

    // loader mapping: 4 threads per 16-wide k-row, 64 rows per pass, 2 passes
    const int lr = tid >> 2;           // 0..63
    const int lc = (tid & 3) << 2;     // 0,4,8,12

    float acc[TM][TN];
    #pragma unroll
    for (int i = 0; i < TM; i++)
        #pragma unroll
        for (int j = 0; j < TN; j++)
            acc[i][j] = 0.0f;

    for (int k0 = 0; k0 < K; k0 += BK) {
        #pragma unroll
        for (int p = 0; p < 2; p++) {
            int r = lr + p * 64;
            float4 va = *reinterpret_cast<const float4*>(&Ab[(size_t)(row0 + r) * K + k0 + lc]);
            As[lc + 0][r] = va.x; As[lc + 1][r] = va.y;
            As[lc + 2][r] = va.z; As[lc + 3][r] = va.w;
            float4 vb = *reinterpret_cast<const float4*>(&Bb[(size_t)(col0 + r) * K + k0 + lc]);
            Bs[lc + 0][r] = vb.x; Bs[lc + 1][r] = vb.y;
            Bs[lc + 2][r] = vb.z; Bs[lc + 3][r] = vb.w;
        }
        __syncthreads();

        #pragma unroll
        for (int kk = 0; kk < BK; kk++) {
            float a[TM], b[TN];
            #pragma unroll
            for (int i = 0; i < TM; i++) a[i] = As[kk][ty * TM + i];
            #pragma unroll
            for (int j = 0; j < TN; j++) b[j] = Bs[kk][tx * TN + j];
            #pragma unroll
            for (int i = 0; i < TM; i++)
                #pragma unroll
                for (int j = 0; j < TN; j++)
                    acc[i][j] = fmaf(a[i], b[j], acc[i][j]);
        }
        __syncthreads();
    }

    #pragma unroll
    for (int i = 0; i < TM; i++) {
        int r = row0 + ty * TM + i;
        #pragma unroll
        for (int j = 0; j < TN; j += 4) {
            float4 v = make_float4(acc[i][j], acc[i][j + 1], acc[i][j + 2], acc[i][j + 3]);
            *reinterpret_cast<float4*>(&Cb[(size_t)r * N + col0 + tx * TN + j]) = v;
        }
    }
}

// ---------------------------------------------------------------------------
// C[M,N] = A[M,K] * B[K,N]    (both row-major; "NN" gemm)
// grid: (N/BN, M/BM, batch).  B batch stride = K*N (Key reused: K=Tk, N=D).
// ---------------------------------------------------------------------------
__global__ __launch_bounds__(NTHREADS) void sgemm_nn_kernel(
    const float* __restrict__ A, const float* __restrict__ Bm, float* __restrict__ C,
    int M, int N, int K)
{
    const float* Ab = A  + (size_t)blockIdx.z * M * K;
    const float* Bb = Bm + (size_t)blockIdx.z * K * N;
    float*       Cb = C  + (size_t)blockIdx.z * M * N;

    __shared__ float As[BK][BM];
    __shared__ float Bs[BK][BN];

    const int tid = threadIdx.x;
    const int ty  = tid / (BN / TN);
    const int tx  = tid % (BN / TN);

    const int row0 = blockIdx.y * BM;
    const int col0 = blockIdx.x * BN;

    // A loader: same as NT (transpose 128x16 into As)
    const int lr = tid >> 2;
    const int lc = (tid & 3) << 2;
    // B loader: 16 rows x 128 cols, direct copy. 32 float4 per row.
    const int br = tid >> 5;           // 0..7
    const int bc = (tid & 31) << 2;    // 0..124

    float acc[TM][TN];
    #pragma unroll
    for (int i = 0; i < TM; i++)
        #pragma unroll
        for (int j = 0; j < TN; j++)
            acc[i][j] = 0.0f;

    for (int k0 = 0; k0 < K; k0 += BK) {
        #pragma unroll
        for (int p = 0; p < 2; p++) {
            int r = lr + p * 64;
            float4 va = *reinterpret_cast<const float4*>(&Ab[(size_t)(row0 + r) * K + k0 + lc]);
            As[lc + 0][r] = va.x; As[lc + 1][r] = va.y;
            As[lc + 2][r] = va.z; As[lc + 3][r] = va.w;

            int kr = br + p * 8;
            float4 vb = *reinterpret_cast<const float4*>(&Bb[(size_t)(k0 + kr) * N + col0 + bc]);
            *reinterpret_cast<float4*>(&Bs[kr][bc]) = vb;
        }
        __syncthreads();

        #pragma unroll
        for (int kk = 0; kk < BK; kk++) {
            float a[TM], b[TN];
            #pragma unroll
            for (int i = 0; i < TM; i++) a[i] = As[kk][ty * TM + i];
            #pragma unroll
            for (int j = 0; j < TN; j++) b[j] = Bs[kk][tx * TN + j];
            #pragma unroll
            for (int i = 0; i < TM; i++)
                #pragma unroll
                for (int j = 0; j < TN; j++)
                    acc[i][j] = fmaf(a[i], b[j], acc[i][j]);
        }
        __syncthreads();
    }

    #pragma unroll
    for (int i = 0; i < TM; i++) {
        int r = row0 + ty * TM + i;
        #pragma unroll
        for (int j = 0; j < TN; j += 4) {
            float4 v = make_float4(acc[i][j], acc[i][j + 1], acc[i][j + 2], acc[i][j + 3]);
            *reinterpret_cast<float4*>(&Cb[(size_t)r * N + col0 + tx * TN + j]) = v;
        }
    }
}

// ---------------------------------------------------------------------------
// In-place row softmax over N=2048 elements. One 256-thread block per row.
// ---------------------------------------------------------------------------
__global__ __launch_bounds__(256) void softmax_kernel(float* __restrict__ E, int N)
{
    float4* row = reinterpret_cast<float4*>(E + (size_t)blockIdx.x * N);
    const int t = threadIdx.x;

    float4 v0 = row[t];
    float4 v1 = row[t + 256];

    float m = fmaxf(fmaxf(fmaxf(v0.x, v0.y), fmaxf(v0.z, v0.w)),
                    fmaxf(fmaxf(v1.x, v1.y), fmaxf(v1.z, v1.w)));

    __shared__ float red[8];
    #pragma unroll
    for (int o = 16; o > 0; o >>= 1) m = fmaxf(m, __shfl_xor_sync(0xFFFFFFFFu, m, o));
    if ((t & 31) == 0) red[t >> 5] = m;
    __syncthreads();
    m = red[0];
    #pragma unroll
    for (int w = 1; w < 8; w++) m = fmaxf(m, red[w]);

    float4 e0, e1;
    e0.x = __expf(v0.x - m); e0.y = __expf(v0.y - m);
    e0.z = __expf(v0.z - m); e0.w = __expf(v0.w - m);
    e1.x = __expf(v1.x - m); e1.y = __expf(v1.y - m);
    e1.z = __expf(v1.z - m); e1.w = __expf(v1.w - m);

    float s = (e0.x + e0.y + e0.z + e0.w) + (e1.x + e1.y + e1.z + e1.w);
    #pragma unroll
    for (int o = 16; o > 0; o >>= 1) s += __shfl_xor_sync(0xFFFFFFFFu, s, o);
    __syncthreads();  // red[] reuse
    if ((t & 31) == 0) red[t >> 5] = s;
    __syncthreads();
    s = 0.0f;
    #pragma unroll
    for (int w = 0; w < 8; w++) s += red[w];

    float inv = 1.0f / s;
    e0.x *= inv; e0.y *= inv; e0.z *= inv; e0.w *= inv;
    e1.x *= inv; e1.y *= inv; e1.z *= inv; e1.w *= inv;
    row[t]       = e0;
    row[t + 256] = e1;
}

// ---------------------------------------------------------------------------
extern "C" void kernel_launch(void* const* d_in, const int* in_sizes, int n_in,
                              void* d_out, int out_size)
{
    const float* q   = (const float*)d_in[0];
    const float* key = (const float*)d_in[1];
    float*       out = (float*)d_out;

    float* energy = nullptr;
    cudaGetSymbolAddress((void**)&energy, g_energy);

    // E = Q @ K^T : M=TQ, N=TK, inner=DIM
    dim3 g1(TK / BN, TQ / BM, BATCH);
    sgemm_nt_kernel<<<g1, NTHREADS>>>(q, key, energy, TQ, TK, DIM);

    // softmax over rows of E
    softmax_kernel<<<BATCH * TQ, 256>>>(energy, TK);

    // out = P @ K : M=TQ, N=DIM, inner=TK  (B batch stride = TK*DIM = K*N, matches Key)
    dim3 g3(DIM / BN, TQ / BM, BATCH);
    sgemm_nn_kernel<<<g3, NTHREADS>>>(energy, key, out, TQ, DIM, TK);
}

// round 3
// speedup vs baseline: 1.7400x; 1.7400x over previous
#include <cuda_runtime.h>
#include <cstdint>

static const int BATCH = 8;
static const int TQ    = 2048;
static const int TK    = 2048;
static const int DIM   = 1024;

// 128 MiB scratch for energy / probabilities [B, Tq, Tk]
__device__ float g_energy[(size_t)8 * 2048 * 2048];

__device__ __forceinline__ float tf32r(float x) {
    uint32_t u;
    asm("cvt.rna.tf32.f32 %0, %1;" : "=r"(u) : "f"(x));
    return __uint_as_float(u);
}

__device__ __forceinline__ void mma_tf32(float* d, const uint32_t* a, const uint32_t* b) {
    asm volatile(
        "mma.sync.aligned.m16n8k8.row.col.f32.tf32.tf32.f32 "
        "{%0,%1,%2,%3}, {%4,%5,%6,%7}, {%8,%9}, {%0,%1,%2,%3};"
        : "+f"(d[0]), "+f"(d[1]), "+f"(d[2]), "+f"(d[3])
        : "r"(a[0]), "r"(a[1]), "r"(a[2]), "r"(a[3]), "r"(b[0]), "r"(b[1]));
}

#define BM 128
#define BN 128
#define BK 16
#define LDS_PAD 136   // 16 rows x 136 floats; (8*k + m) % 32 distinct -> conflict-free frags

// ---------------------------------------------------------------------------
// QK: E[128x128] = Q_tile[128x1024] @ K_tile[128x1024]^T, 3x tf32 split.
// Both A and B are K-major in gmem; both stored transposed As[k][m], Bs[k][n].
// 256 threads, 8 warps, warp tile 64x32 (warp_m = wid>>2 in 0..1, warp_n = wid&3).
// ---------------------------------------------------------------------------
__global__ __launch_bounds__(256) void qk_kernel(const float* __restrict__ Q,
                                                 const float* __restrict__ Km,
                                                 float* __restrict__ E)
{
    __shared__ float As[2][BK][LDS_PAD];
    __shared__ float Bs[2][BK][LDS_PAD];

    const int tid  = threadIdx.x;
    const int wid  = tid >> 5, lane = tid & 31;
    const int gid  = lane >> 2, tig = lane & 3;
    const int wm   = (wid >> 2) * 64;     // warp m base
    const int wn   = (wid & 3) * 32;      // warp n base
    const int row0 = blockIdx.y * BM, col0 = blockIdx.x * BN;

    const float* Qb = Q  + (size_t)blockIdx.z * TQ * DIM;
    const float* Kb = Km + (size_t)blockIdx.z * TK * DIM;
    float*       Eb = E  + (size_t)blockIdx.z * TQ * TK;

    // loader: idx = tid + p*256 -> r = idx>>2 (0..127), c4 = idx&3 (col group)
    const int lr0 = tid >> 2, lc0 = (tid & 3) * 4;

    float acc[4][4][4];
    #pragma unroll
    for (int i = 0; i < 4; i++)
        #pragma unroll
        for (int j = 0; j < 4; j++)
            #pragma unroll
            for (int c = 0; c < 4; c++) acc[i][j][c] = 0.0f;

    const int NIT = DIM / BK;  // 64
    float4 av[2], bv[2];

    // prologue: iter 0 -> buf 0
    #pragma unroll
    for (int p = 0; p < 2; p++) {
        av[p] = *reinterpret_cast<const float4*>(&Qb[(size_t)(row0 + lr0 + p * 64) * DIM + lc0]);
        bv[p] = *reinterpret_cast<const float4*>(&Kb[(size_t)(col0 + lr0 + p * 64) * DIM + lc0]);
    }
    #pragma unroll
    for (int p = 0; p < 2; p++) {
        int r = lr0 + p * 64;
        As[0][lc0 + 0][r] = av[p].x; As[0][lc0 + 1][r] = av[p].y;
        As[0][lc0 + 2][r] = av[p].z; As[0][lc0 + 3][r] = av[p].w;
        Bs[0][lc0 + 0][r] = bv[p].x; Bs[0][lc0 + 1][r] = bv[p].y;
        Bs[0][lc0 + 2][r] = bv[p].z; Bs[0][lc0 + 3][r] = bv[p].w;
    }
    __syncthreads();

    int buf = 0;
    for (int it = 0; it < NIT; it++) {
        if (it + 1 < NIT) {
            int k0 = (it + 1) * BK;
            #pragma unroll
            for (int p = 0; p < 2; p++) {
                av[p] = *reinterpret_cast<const float4*>(&Qb[(size_t)(row0 + lr0 + p * 64) * DIM + k0 + lc0]);
                bv[p] = *reinterpret_cast<const float4*>(&Kb[(size_t)(col0 + lr0 + p * 64) * DIM + k0 + lc0]);
            }
        }

        #pragma unroll
        for (int ks = 0; ks < BK; ks += 8) {
            uint32_t ahi[4][4], alo[4][4], bhi[4][2], blo[4][2];
            #pragma unroll
            for (int mi = 0; mi < 4; mi++) {
                int m0 = wm + mi * 16;
                float r0 = As[buf][ks + tig    ][m0 + gid];
                float r1 = As[buf][ks + tig    ][m0 + gid + 8];
                float r2 = As[buf][ks + tig + 4][m0 + gid];
                float r3 = As[buf][ks + tig + 4][m0 + gid + 8];
                float h;
                h = tf32r(r0); ahi[mi][0] = __float_as_uint(h); alo[mi][0] = __float_as_uint(tf32r(r0 - h));
                h = tf32r(r1); ahi[mi][1] = __float_as_uint(h); alo[mi][1] = __float_as_uint(tf32r(r1 - h));
                h = tf32r(r2); ahi[mi][2] = __float_as_uint(h); alo[mi][2] = __float_as_uint(tf32r(r2 - h));
                h = tf32r(r3); ahi[mi][3] = __float_as_uint(h); alo[mi][3] = __float_as_uint(tf32r(r3 - h));
            }
            #pragma unroll
            for (int ni = 0; ni < 4; ni++) {
                int n0 = wn + ni * 8;
                float r0 = Bs[buf][ks + tig    ][n0 + gid];
                float r1 = Bs[buf][ks + tig + 4][n0 + gid];
                float h;
                h = tf32r(r0); bhi[ni][0] = __float_as_uint(h); blo[ni][0] = __float_as_uint(tf32r(r0 - h));
                h = tf32r(r1); bhi[ni][1] = __float_as_uint(h); blo[ni][1] = __float_as_uint(tf32r(r1 - h));
            }
            #pragma unroll
            for (int mi = 0; mi < 4; mi++)
                #pragma unroll
                for (int ni = 0; ni < 4; ni++) {
                    mma_tf32(acc[mi][ni], ahi[mi], bhi[ni]);
                    mma_tf32(acc[mi][ni], ahi[mi], blo[ni]);
                    mma_tf32(acc[mi][ni], alo[mi], bhi[ni]);
                }
        }

        if (it + 1 < NIT) {
            #pragma unroll
            for (int p = 0; p < 2; p++) {
                int r = lr0 + p * 64;
                As[buf ^ 1][lc0 + 0][r] = av[p].x; As[buf ^ 1][lc0 + 1][r] = av[p].y;
                As[buf ^ 1][lc0 + 2][r] = av[p].z; As[buf ^ 1][lc0 + 3][r] = av[p].w;
                Bs[buf ^ 1][lc0 + 0][r] = bv[p].x; Bs[buf ^ 1][lc0 + 1][r] = bv[p].y;
                Bs[buf ^ 1][lc0 + 2][r] = bv[p].z; Bs[buf ^ 1][lc0 + 3][r] = bv[p].w;
            }
            __syncthreads();
            buf ^= 1;
        }
    }

    #pragma unroll
    for (int mi = 0; mi < 4; mi++) {
        #pragma unroll
        for (int ni = 0; ni < 4; ni++) {
            int r = row0 + wm + mi * 16 + gid;
            int c = col0 + wn + ni * 8 + 2 * tig;
            float2 v0 = make_float2(acc[mi][ni][0], acc[mi][ni][1]);
            float2 v1 = make_float2(acc[mi][ni][2], acc[mi][ni][3]);
            *reinterpret_cast<float2*>(&Eb[(size_t)r * TK + c])       = v0;
            *reinterpret_cast<float2*>(&Eb[(size_t)(r + 8) * TK + c]) = v1;
        }
    }
}

// ---------------------------------------------------------------------------
// PV: out[128x128] = P_tile[128x2048] @ Key[2048x1024] (B is k-major rows ->
// direct copy into Bs[k][n]). 1x tf32.
// ---------------------------------------------------------------------------
__global__ __launch_bounds__(256) void pv_kernel(const float* __restrict__ P,
                                                 const float* __restrict__ V,
                                                 float* __restrict__ O)
{
    __shared__ float As[2][BK][LDS_PAD];
    __shared__ float Bs[2][BK][LDS_PAD];

    const int tid  = threadIdx.x;
    const int wid  = tid >> 5, lane = tid & 31;
    const int gid  = lane >> 2, tig = lane & 3;
    const int wm   = (wid >> 2) * 64;
    const int wn   = (wid & 3) * 32;
    const int row0 = blockIdx.y * BM, col0 = blockIdx.x * BN;

    const float* Pb = P + (size_t)blockIdx.z * TQ * TK;
    const float* Vb = V + (size_t)blockIdx.z * TK * DIM;
    float*       Ob = O + (size_t)blockIdx.z * TQ * DIM;

    const int lr0 = tid >> 2, lc0 = (tid & 3) * 4;      // A loader (transpose)
    const int bkr0 = tid >> 5, bnc0 = (tid & 31) * 4;   // B loader (direct)

    float acc[4][4][4];
    #pragma unroll
    for (int i = 0; i < 4; i++)
        #pragma unroll
        for (int j = 0; j < 4; j++)
            #pragma unroll
            for (int c = 0; c < 4; c++) acc[i][j][c] = 0.0f;

    const int NIT = TK / BK;  // 128
    float4 av[2], bv[2];

    #pragma unroll
    for (int p = 0; p < 2; p++) {
        av[p] = *reinterpret_cast<const float4*>(&Pb[(size_t)(row0 + lr0 + p * 64) * TK + lc0]);
        bv[p] = *reinterpret_cast<const float4*>(&Vb[(size_t)(bkr0 + p * 8) * DIM + col0 + bnc0]);
    }
    #pragma unroll
    for (int p = 0; p < 2; p++) {
        int r = lr0 + p * 64;
        As[0][lc0 + 0][r] = av[p].x; As[0][lc0 + 1][r] = av[p].y;
        As[0][lc0 + 2][r] = av[p].z; As[0][lc0 + 3][r] = av[p].w;
        *reinterpret_cast<float4*>(&Bs[0][bkr0 + p * 8][bnc0]) = bv[p];
    }
    __syncthreads();

    int buf = 0;
    for (int it = 0; it < NIT; it++) {
        if (it + 1 < NIT) {
            int k0 = (it + 1) * BK;
            #pragma unroll
            for (int p = 0; p < 2; p++) {
                av[p] = *reinterpret_cast<const float4*>(&Pb[(size_t)(row0 + lr0 + p * 64) * TK + k0 + lc0]);
                bv[p] = *reinterpret_cast<const float4*>(&Vb[(size_t)(k0 + bkr0 + p * 8) * DIM + col0 + bnc0]);
            }
        }

        #pragma unroll
        for (int ks = 0; ks < BK; ks += 8) {
            uint32_t a[4][4], b[4][2];
            #pragma unroll
            for (int mi = 0; mi < 4; mi++) {
                int m0 = wm + mi * 16;
                a[mi][0] = __float_as_uint(tf32r(As[buf][ks + tig    ][m0 + gid]));
                a[mi][1] = __float_as_uint(tf32r(As[buf][ks + tig    ][m0 + gid + 8]));
                a[mi][2] = __float_as_uint(tf32r(As[buf][ks + tig + 4][m0 + gid]));
                a[mi][3] = __float_as_uint(tf32r(As[buf][ks + tig + 4][m0 + gid + 8]));
            }
            #pragma unroll
            for (int ni = 0; ni < 4; ni++) {
                int n0 = wn + ni * 8;
                b[ni][0] = __float_as_uint(tf32r(Bs[buf][ks + tig    ][n0 + gid]));
                b[ni][1] = __float_as_uint(tf32r(Bs[buf][ks + tig + 4][n0 + gid]));
            }
            #pragma unroll
            for (int mi = 0; mi < 4; mi++)
                #pragma unroll
                for (int ni = 0; ni < 4; ni++)
                    mma_tf32(acc[mi][ni], a[mi], b[ni]);
        }

        if (it + 1 < NIT) {
            #pragma unroll
            for (int p = 0; p < 2; p++) {
                int r = lr0 + p * 64;
                As[buf ^ 1][lc0 + 0][r] = av[p].x; As[buf ^ 1][lc0 + 1][r] = av[p].y;
                As[buf ^ 1][lc0 + 2][r] = av[p].z; As[buf ^ 1][lc0 + 3][r] = av[p].w;
                *reinterpret_cast<float4*>(&Bs[buf ^ 1][bkr0 + p * 8][bnc0]) = bv[p];
            }
            __syncthreads();
            buf ^= 1;
        }
    }

    #pragma unroll
    for (int mi = 0; mi < 4; mi++) {
        #pragma unroll
        for (int ni = 0; ni < 4; ni++) {
            int r = row0 + wm + mi * 16 + gid;
            int c = col0 + wn + ni * 8 + 2 * tig;
            float2 v0 = make_float2(acc[mi][ni][0], acc[mi][ni][1]);
            float2 v1 = make_float2(acc[mi][ni][2], acc[mi][ni][3]);
            *reinterpret_cast<float2*>(&Ob[(size_t)r * DIM + c])       = v0;
            *reinterpret_cast<float2*>(&Ob[(size_t)(r + 8) * DIM + c]) = v1;
        }
    }
}

// ---------------------------------------------------------------------------
// In-place row softmax over N=2048 elements (known-good from round 1).
// ---------------------------------------------------------------------------
__global__ __launch_bounds__(256) void softmax_kernel(float* __restrict__ E, int N)
{
    float4* row = reinterpret_cast<float4*>(E + (size_t)blockIdx.x * N);
    const int t = threadIdx.x;

    float4 v0 = row[t];
    float4 v1 = row[t + 256];

    float m = fmaxf(fmaxf(fmaxf(v0.x, v0.y), fmaxf(v0.z, v0.w)),
                    fmaxf(fmaxf(v1.x, v1.y), fmaxf(v1.z, v1.w)));

    __shared__ float red[8];
    #pragma unroll
    for (int o = 16; o > 0; o >>= 1) m = fmaxf(m, __shfl_xor_sync(0xFFFFFFFFu, m, o));
    if ((t & 31) == 0) red[t >> 5] = m;
    __syncthreads();
    m = red[0];
    #pragma unroll
    for (int w = 1; w < 8; w++) m = fmaxf(m, red[w]);

    float4 e0, e1;
    e0.x = __expf(v0.x - m); e0.y = __expf(v0.y - m);
    e0.z = __expf(v0.z - m); e0.w = __expf(v0.w - m);
    e1.x = __expf(v1.x - m); e1.y = __expf(v1.y - m);
    e1.z = __expf(v1.z - m); e1.w = __expf(v1.w - m);

    float s = (e0.x + e0.y + e0.z + e0.w) + (e1.x + e1.y + e1.z + e1.w);
    #pragma unroll
    for (int o = 16; o > 0; o >>= 1) s += __shfl_xor_sync(0xFFFFFFFFu, s, o);
    __syncthreads();
    if ((t & 31) == 0) red[t >> 5] = s;
    __syncthreads();
    s = 0.0f;
    #pragma unroll
    for (int w = 0; w < 8; w++) s += red[w];

    float inv = 1.0f / s;
    e0.x *= inv; e0.y *= inv; e0.z *= inv; e0.w *= inv;
    e1.x *= inv; e1.y *= inv; e1.z *= inv; e1.w *= inv;
    row[t]       = e0;
    row[t + 256] = e1;
}

// ---------------------------------------------------------------------------
extern "C" void kernel_launch(void* const* d_in, const int* in_sizes, int n_in,
                              void* d_out, int out_size)
{
    const float* q   = (const float*)d_in[0];
    const float* key = (const float*)d_in[1];
    float*       out = (float*)d_out;

    float* energy = nullptr;
    cudaGetSymbolAddress((void**)&energy, g_energy);

    dim3 g1(TK / BN, TQ / BM, BATCH);
    qk_kernel<<<g1, 256>>>(q, key, energy);

    softmax_kernel<<<BATCH * TQ, 256>>>(energy, TK);

    dim3 g2(DIM / BN, TQ / BM, BATCH);
    pv_kernel<<<g2, 256>>>(energy, key, out);
}

// round 4
// speedup vs baseline: 2.9181x; 1.6771x over previous
#include <cuda_runtime.h>
#include <cstdint>

static const int BATCH = 8;
static const int TQ    = 2048;
static const int TK    = 2048;
static const int DIM   = 1024;

// 128 MiB scratch for energy / probabilities [B, Tq, Tk]
__device__ float g_energy[(size_t)8 * 2048 * 2048];

// ---------------------------------------------------------------------------
__device__ __forceinline__ float tf32r(float x) {
    uint32_t u;
    asm("cvt.rna.tf32.f32 %0, %1;" : "=r"(u) : "f"(x));
    return __uint_as_float(u);
}

__device__ __forceinline__ void mma_tf32(float* d, const uint32_t* a, const uint32_t* b) {
    asm volatile(
        "mma.sync.aligned.m16n8k8.row.col.f32.tf32.tf32.f32 "
        "{%0,%1,%2,%3}, {%4,%5,%6,%7}, {%8,%9}, {%0,%1,%2,%3};"
        : "+f"(d[0]), "+f"(d[1]), "+f"(d[2]), "+f"(d[3])
        : "r"(a[0]), "r"(a[1]), "r"(a[2]), "r"(a[3]), "r"(b[0]), "r"(b[1]));
}

__device__ __forceinline__ void mma_bf16(float* d, const uint32_t* a, const uint32_t* b) {
    asm volatile(
        "mma.sync.aligned.m16n8k16.row.col.f32.bf16.bf16.f32 "
        "{%0,%1,%2,%3}, {%4,%5,%6,%7}, {%8,%9}, {%0,%1,%2,%3};"
        : "+f"(d[0]), "+f"(d[1]), "+f"(d[2]), "+f"(d[3])
        : "r"(a[0]), "r"(a[1]), "r"(a[2]), "r"(a[3]), "r"(b[0]), "r"(b[1]));
}

// Dekker split of 4 floats into bf16x2 hi pairs and lo pairs (low half = even idx)
__device__ __forceinline__ void bf16_split_pack(float4 v, uint32_t& h01, uint32_t& h23,
                                                uint32_t& l01, uint32_t& l23) {
    asm("cvt.rn.bf16x2.f32 %0, %1, %2;" : "=r"(h01) : "f"(v.y), "f"(v.x));
    asm("cvt.rn.bf16x2.f32 %0, %1, %2;" : "=r"(h23) : "f"(v.w), "f"(v.z));
    float hx = __uint_as_float(h01 << 16);
    float hy = __uint_as_float(h01 & 0xFFFF0000u);
    float hz = __uint_as_float(h23 << 16);
    float hw = __uint_as_float(h23 & 0xFFFF0000u);
    asm("cvt.rn.bf16x2.f32 %0, %1, %2;" : "=r"(l01) : "f"(v.y - hy), "f"(v.x - hx));
    asm("cvt.rn.bf16x2.f32 %0, %1, %2;" : "=r"(l23) : "f"(v.w - hw), "f"(v.z - hz));
}

// ---------------------------------------------------------------------------
// QK: E tile [128 x 256] = Q[128 x 1024] @ K[256 x 1024]^T, 3x bf16 split.
// 512 threads (16 warps), warp grid 4x4, warp tile 32x64. BK=16 (one k16 mma).
// smem (dynamic, 51200 B): AH/AL [2][8][136] u32 pairs, BH/BL [2][8][264].
// ---------------------------------------------------------------------------
#define QK_SMEM 51200
#define APITCH 136
#define BPITCH 264

__global__ __launch_bounds__(512, 1) void qk_kernel(const float* __restrict__ Q,
                                                    const float* __restrict__ Km,
                                                    float* __restrict__ E)
{
    extern __shared__ uint32_t dsm[];
    uint32_t* AH = dsm;                 // [2][8*136]
    uint32_t* AL = AH + 2 * 8 * APITCH;
    uint32_t* BH = AL + 2 * 8 * APITCH; // [2][8*264]
    uint32_t* BL = BH + 2 * 8 * BPITCH;

    const int tid = threadIdx.x, wid = tid >> 5, lane = tid & 31;
    const int gid = lane >> 2, tig = lane & 3;
    const int wm = (wid >> 2) * 32, wn = (wid & 3) * 64;
    const int row0 = blockIdx.y * 128, col0 = blockIdx.x * 256;

    const float* Qb = Q  + (size_t)blockIdx.z * TQ * DIM;
    const float* Kb = Km + (size_t)blockIdx.z * TK * DIM;
    float*       Eb = E  + (size_t)blockIdx.z * TQ * TK;

    // loaders: each thread: 1 float4 of A (128x16), 2 float4 of B (256x16)
    const int lr  = tid >> 2;           // 0..127
    const int lk2 = (tid & 3) * 2;      // k-pair index 0,2,4,6
    const int lkc = (tid & 3) * 4;      // k float offset

    float acc[2][8][4];
    #pragma unroll
    for (int i = 0; i < 2; i++)
        #pragma unroll
        for (int j = 0; j < 8; j++)
            #pragma unroll
            for (int c = 0; c < 4; c++) acc[i][j][c] = 0.0f;

    const int NIT = DIM / 16;  // 64
    float4 av, bv0, bv1;

    av  = *reinterpret_cast<const float4*>(&Qb[(size_t)(row0 + lr) * DIM + lkc]);
    bv0 = *reinterpret_cast<const float4*>(&Kb[(size_t)(col0 + lr) * DIM + lkc]);
    bv1 = *reinterpret_cast<const float4*>(&Kb[(size_t)(col0 + 128 + lr) * DIM + lkc]);
    {
        uint32_t h01, h23, l01, l23;
        bf16_split_pack(av, h01, h23, l01, l23);
        AH[lk2 * APITCH + lr] = h01; AH[(lk2 + 1) * APITCH + lr] = h23;
        AL[lk2 * APITCH + lr] = l01; AL[(lk2 + 1) * APITCH + lr] = l23;
        bf16_split_pack(bv0, h01, h23, l01, l23);
        BH[lk2 * BPITCH + lr] = h01; BH[(lk2 + 1) * BPITCH + lr] = h23;
        BL[lk2 * BPITCH + lr] = l01; BL[(lk2 + 1) * BPITCH + lr] = l23;
        bf16_split_pack(bv1, h01, h23, l01, l23);
        BH[lk2 * BPITCH + 128 + lr] = h01; BH[(lk2 + 1) * BPITCH + 128 + lr] = h23;
        BL[lk2 * BPITCH + 128 + lr] = l01; BL[(lk2 + 1) * BPITCH + 128 + lr] = l23;
    }
    __syncthreads();

    int buf = 0;
    for (int it = 0; it < NIT; it++) {
        if (it + 1 < NIT) {
            int k0 = (it + 1) * 16;
            av  = *reinterpret_cast<const float4*>(&Qb[(size_t)(row0 + lr) * DIM + k0 + lkc]);
            bv0 = *reinterpret_cast<const float4*>(&Kb[(size_t)(col0 + lr) * DIM + k0 + lkc]);
            bv1 = *reinterpret_cast<const float4*>(&Kb[(size_t)(col0 + 128 + lr) * DIM + k0 + lkc]);
        }

        const uint32_t* pAH = AH + buf * 8 * APITCH;
        const uint32_t* pAL = AL + buf * 8 * APITCH;
        const uint32_t* pBH = BH + buf * 8 * BPITCH;
        const uint32_t* pBL = BL + buf * 8 * BPITCH;

        uint32_t aH[2][4], aL[2][4];
        #pragma unroll
        for (int mi = 0; mi < 2; mi++) {
            int m = wm + mi * 16 + gid;
            aH[mi][0] = pAH[tig * APITCH + m];
            aH[mi][1] = pAH[tig * APITCH + m + 8];
            aH[mi][2] = pAH[(tig + 4) * APITCH + m];
            aH[mi][3] = pAH[(tig + 4) * APITCH + m + 8];
            aL[mi][0] = pAL[tig * APITCH + m];
            aL[mi][1] = pAL[tig * APITCH + m + 8];
            aL[mi][2] = pAL[(tig + 4) * APITCH + m];
            aL[mi][3] = pAL[(tig + 4) * APITCH + m + 8];
        }
        #pragma unroll
        for (int ni = 0; ni < 8; ni++) {
            int n = wn + ni * 8 + gid;
            uint32_t bh[2], bl[2];
            bh[0] = pBH[tig * BPITCH + n];
            bh[1] = pBH[(tig + 4) * BPITCH + n];
            bl[0] = pBL[tig * BPITCH + n];
            bl[1] = pBL[(tig + 4) * BPITCH + n];
            #pragma unroll
            for (int mi = 0; mi < 2; mi++) {
                mma_bf16(acc[mi][ni], aH[mi], bh);
                mma_bf16(acc[mi][ni], aH[mi], bl);
                mma_bf16(acc[mi][ni], aL[mi], bh);
            }
        }

        if (it + 1 < NIT) {
            uint32_t* qAH = AH + (buf ^ 1) * 8 * APITCH;
            uint32_t* qAL = AL + (buf ^ 1) * 8 * APITCH;
            uint32_t* qBH = BH + (buf ^ 1) * 8 * BPITCH;
            uint32_t* qBL = BL + (buf ^ 1) * 8 * BPITCH;
            uint32_t h01, h23, l01, l23;
            bf16_split_pack(av, h01, h23, l01, l23);
            qAH[lk2 * APITCH + lr] = h01; qAH[(lk2 + 1) * APITCH + lr] = h23;
            qAL[lk2 * APITCH + lr] = l01; qAL[(lk2 + 1) * APITCH + lr] = l23;
            bf16_split_pack(bv0, h01, h23, l01, l23);
            qBH[lk2 * BPITCH + lr] = h01; qBH[(lk2 + 1) * BPITCH + lr] = h23;
            qBL[lk2 * BPITCH + lr] = l01; qBL[(lk2 + 1) * BPITCH + lr] = l23;
            bf16_split_pack(bv1, h01, h23, l01, l23);
            qBH[lk2 * BPITCH + 128 + lr] = h01; qBH[(lk2 + 1) * BPITCH + 128 + lr] = h23;
            qBL[lk2 * BPITCH + 128 + lr] = l01; qBL[(lk2 + 1) * BPITCH + 128 + lr] = l23;
            __syncthreads();
            buf ^= 1;
        }
    }

    #pragma unroll
    for (int mi = 0; mi < 2; mi++) {
        #pragma unroll
        for (int ni = 0; ni < 8; ni++) {
            int r = row0 + wm + mi * 16 + gid;
            int c = col0 + wn + ni * 8 + 2 * tig;
            float2 v0 = make_float2(acc[mi][ni][0], acc[mi][ni][1]);
            float2 v1 = make_float2(acc[mi][ni][2], acc[mi][ni][3]);
            *reinterpret_cast<float2*>(&Eb[(size_t)r * TK + c])       = v0;
            *reinterpret_cast<float2*>(&Eb[(size_t)(r + 8) * TK + c]) = v1;
        }
    }
}

// ---------------------------------------------------------------------------
// PV: out tile [128 x 256] = P[128 x 2048] @ Key[2048 x 256-slice], 1x tf32.
// 512 threads (16 warps), warp grid 2x8, warp tile 64x32. BK=16 (2 k8 slices).
// smem (dynamic, 51200 B): As [2][16][136] f32 (transposed), Bs [2][16][264] f32.
// ---------------------------------------------------------------------------
#define PV_SMEM 51200
#define PV_APITCH 136
#define PV_BPITCH 264

__global__ __launch_bounds__(512, 1) void pv_kernel(const float* __restrict__ P,
                                                    const float* __restrict__ V,
                                                    float* __restrict__ O)
{
    extern __shared__ float fsm[];
    float* As = fsm;                     // [2][16*136]
    float* Bs = As + 2 * 16 * PV_APITCH; // [2][16*264]

    const int tid = threadIdx.x, wid = tid >> 5, lane = tid & 31;
    const int gid = lane >> 2, tig = lane & 3;
    const int wm = (wid >> 3) * 64, wn = (wid & 7) * 32;
    const int row0 = blockIdx.y * 128, col0 = blockIdx.x * 256;

    const float* Pb = P + (size_t)blockIdx.z * TQ * TK;
    const float* Vb = V + (size_t)blockIdx.z * TK * DIM;
    float*       Ob = O + (size_t)blockIdx.z * TQ * DIM;

    const int ar  = tid >> 2;          // 0..127
    const int ac4 = (tid & 3) * 4;     // k offset
    const int bkr = tid >> 6;          // 0..7 (two passes -> 0..15)
    const int bnc = (tid & 63) * 4;    // 0..252

    float acc[4][4][4];
    #pragma unroll
    for (int i = 0; i < 4; i++)
        #pragma unroll
        for (int j = 0; j < 4; j++)
            #pragma unroll
            for (int c = 0; c < 4; c++) acc[i][j][c] = 0.0f;

    const int NIT = TK / 16;  // 128
    float4 av, bv0, bv1;

    av  = *reinterpret_cast<const float4*>(&Pb[(size_t)(row0 + ar) * TK + ac4]);
    bv0 = *reinterpret_cast<const float4*>(&Vb[(size_t)(bkr) * DIM + col0 + bnc]);
    bv1 = *reinterpret_cast<const float4*>(&Vb[(size_t)(bkr + 8) * DIM + col0 + bnc]);
    {
        As[(ac4 + 0) * PV_APITCH + ar] = av.x; As[(ac4 + 1) * PV_APITCH + ar] = av.y;
        As[(ac4 + 2) * PV_APITCH + ar] = av.z; As[(ac4 + 3) * PV_APITCH + ar] = av.w;
        *reinterpret_cast<float4*>(&Bs[bkr * PV_BPITCH + bnc])       = bv0;
        *reinterpret_cast<float4*>(&Bs[(bkr + 8) * PV_BPITCH + bnc]) = bv1;
    }
    __syncthreads();

    int buf = 0;
    for (int it = 0; it < NIT; it++) {
        if (it + 1 < NIT) {
            int k0 = (it + 1) * 16;
            av  = *reinterpret_cast<const float4*>(&Pb[(size_t)(row0 + ar) * TK + k0 + ac4]);
            bv0 = *reinterpret_cast<const float4*>(&Vb[(size_t)(k0 + bkr) * DIM + col0 + bnc]);
            bv1 = *reinterpret_cast<const float4*>(&Vb[(size_t)(k0 + bkr + 8) * DIM + col0 + bnc]);
        }

        const float* pA = As + buf * 16 * PV_APITCH;
        const float* pB = Bs + buf * 16 * PV_BPITCH;

        #pragma unroll
        for (int ks = 0; ks < 16; ks += 8) {
            uint32_t a[4][4];
            #pragma unroll
            for (int mi = 0; mi < 4; mi++) {
                int m = wm + mi * 16 + gid;
                a[mi][0] = __float_as_uint(tf32r(pA[(ks + tig) * PV_APITCH + m]));
                a[mi][1] = __float_as_uint(tf32r(pA[(ks + tig) * PV_APITCH + m + 8]));
                a[mi][2] = __float_as_uint(tf32r(pA[(ks + tig + 4) * PV_APITCH + m]));
                a[mi][3] = __float_as_uint(tf32r(pA[(ks + tig + 4) * PV_APITCH + m + 8]));
            }
            #pragma unroll
            for (int ni = 0; ni < 4; ni++) {
                int n = wn + ni * 8 + gid;
                uint32_t b[2];
                b[0] = __float_as_uint(tf32r(pB[(ks + tig) * PV_BPITCH + n]));
                b[1] = __float_as_uint(tf32r(pB[(ks + tig + 4) * PV_BPITCH + n]));
                #pragma unroll
                for (int mi = 0; mi < 4; mi++)
                    mma_tf32(acc[mi][ni], a[mi], b);
            }
        }

        if (it + 1 < NIT) {
            float* qA = As + (buf ^ 1) * 16 * PV_APITCH;
            float* qB = Bs + (buf ^ 1) * 16 * PV_BPITCH;
            qA[(ac4 + 0) * PV_APITCH + ar] = av.x; qA[(ac4 + 1) * PV_APITCH + ar] = av.y;
            qA[(ac4 + 2) * PV_APITCH + ar] = av.z; qA[(ac4 + 3) * PV_APITCH + ar] = av.w;
            *reinterpret_cast<float4*>(&qB[bkr * PV_BPITCH + bnc])       = bv0;
            *reinterpret_cast<float4*>(&qB[(bkr + 8) * PV_BPITCH + bnc]) = bv1;
            __syncthreads();
            buf ^= 1;
        }
    }

    #pragma unroll
    for (int mi = 0; mi < 4; mi++) {
        #pragma unroll
        for (int ni = 0; ni < 4; ni++) {
            int r = row0 + wm + mi * 16 + gid;
            int c = col0 + wn + ni * 8 + 2 * tig;
            float2 v0 = make_float2(acc[mi][ni][0], acc[mi][ni][1]);
            float2 v1 = make_float2(acc[mi][ni][2], acc[mi][ni][3]);
            *reinterpret_cast<float2*>(&Ob[(size_t)r * DIM + c])       = v0;
            *reinterpret_cast<float2*>(&Ob[(size_t)(r + 8) * DIM + c]) = v1;
        }
    }
}

// ---------------------------------------------------------------------------
// In-place row softmax over N=2048 elements (known-good).
// ---------------------------------------------------------------------------
__global__ __launch_bounds__(256) void softmax_kernel(float* __restrict__ E, int N)
{
    float4* row = reinterpret_cast<float4*>(E + (size_t)blockIdx.x * N);
    const int t = threadIdx.x;

    float4 v0 = row[t];
    float4 v1 = row[t + 256];

    float m = fmaxf(fmaxf(fmaxf(v0.x, v0.y), fmaxf(v0.z, v0.w)),
                    fmaxf(fmaxf(v1.x, v1.y), fmaxf(v1.z, v1.w)));

    __shared__ float red[8];
    #pragma unroll
    for (int o = 16; o > 0; o >>= 1) m = fmaxf(m, __shfl_xor_sync(0xFFFFFFFFu, m, o));
    if ((t & 31) == 0) red[t >> 5] = m;
    __syncthreads();
    m = red[0];
    #pragma unroll
    for (int w = 1; w < 8; w++) m = fmaxf(m, red[w]);

    float4 e0, e1;
    e0.x = __expf(v0.x - m); e0.y = __expf(v0.y - m);
    e0.z = __expf(v0.z - m); e0.w = __expf(v0.w - m);
    e1.x = __expf(v1.x - m); e1.y = __expf(v1.y - m);
    e1.z = __expf(v1.z - m); e1.w = __expf(v1.w - m);

    float s = (e0.x + e0.y + e0.z + e0.w) + (e1.x + e1.y + e1.z + e1.w);
    #pragma unroll
    for (int o = 16; o > 0; o >>= 1) s += __shfl_xor_sync(0xFFFFFFFFu, s, o);
    __syncthreads();
    if ((t & 31) == 0) red[t >> 5] = s;
    __syncthreads();
    s = 0.0f;
    #pragma unroll
    for (int w = 0; w < 8; w++) s += red[w];

    float inv = 1.0f / s;
    e0.x *= inv; e0.y *= inv; e0.z *= inv; e0.w *= inv;
    e1.x *= inv; e1.y *= inv; e1.z *= inv; e1.w *= inv;
    row[t]       = e0;
    row[t + 256] = e1;
}

// ---------------------------------------------------------------------------
extern "C" void kernel_launch(void* const* d_in, const int* in_sizes, int n_in,
                              void* d_out, int out_size)
{
    const float* q   = (const float*)d_in[0];
    const float* key = (const float*)d_in[1];
    float*       out = (float*)d_out;

    float* energy = nullptr;
    cudaGetSymbolAddress((void**)&energy, g_energy);

    cudaFuncSetAttribute(qk_kernel, cudaFuncAttributeMaxDynamicSharedMemorySize, QK_SMEM);
    cudaFuncSetAttribute(pv_kernel, cudaFuncAttributeMaxDynamicSharedMemorySize, PV_SMEM);

    dim3 g1(TK / 256, TQ / 128, BATCH);
    qk_kernel<<<g1, 512, QK_SMEM>>>(q, key, energy);

    softmax_kernel<<<BATCH * TQ, 256>>>(energy, TK);

    dim3 g2(DIM / 256, TQ / 128, BATCH);
    pv_kernel<<<g2, 512, PV_SMEM>>>(energy, key, out);
}

// round 5
// speedup vs baseline: 3.0705x; 1.0522x over previous
#include <cuda_runtime.h>
#include <cuda_fp16.h>
#include <cstdint>

static const int BATCH = 8;
static const int TQ    = 2048;
static const int TK    = 2048;
static const int DIM   = 1024;

// Scratch: energy f32 (128 MB) + P split into f16 hi/lo (64 MB each)
__device__ float  g_energy[(size_t)8 * 2048 * 2048];
__device__ __half g_phi[(size_t)8 * 2048 * 2048];
__device__ __half g_plo[(size_t)8 * 2048 * 2048];

// ---------------------------------------------------------------------------
__device__ __forceinline__ uint32_t smem_u32(const void* p) {
    uint32_t a;
    asm("{ .reg .u64 t; cvta.to.shared.u64 t, %1; cvt.u32.u64 %0, t; }" : "=r"(a) : "l"(p));
    return a;
}

__device__ __forceinline__ void mma_bf16(float* d, const uint32_t* a, const uint32_t* b) {
    asm volatile(
        "mma.sync.aligned.m16n8k16.row.col.f32.bf16.bf16.f32 "
        "{%0,%1,%2,%3}, {%4,%5,%6,%7}, {%8,%9}, {%0,%1,%2,%3};"
        : "+f"(d[0]), "+f"(d[1]), "+f"(d[2]), "+f"(d[3])
        : "r"(a[0]), "r"(a[1]), "r"(a[2]), "r"(a[3]), "r"(b[0]), "r"(b[1]));
}

__device__ __forceinline__ void mma_f16(float* d, const uint32_t* a, const uint32_t* b) {
    asm volatile(
        "mma.sync.aligned.m16n8k16.row.col.f32.f16.f16.f32 "
        "{%0,%1,%2,%3}, {%4,%5,%6,%7}, {%8,%9}, {%0,%1,%2,%3};"
        : "+f"(d[0]), "+f"(d[1]), "+f"(d[2]), "+f"(d[3])
        : "r"(a[0]), "r"(a[1]), "r"(a[2]), "r"(a[3]), "r"(b[0]), "r"(b[1]));
}

#define LDSM4(r, a) \
    asm volatile("ldmatrix.sync.aligned.m8n8.x4.shared.b16 {%0,%1,%2,%3}, [%4];" \
                 : "=r"((r)[0]), "=r"((r)[1]), "=r"((r)[2]), "=r"((r)[3]) : "r"(a))
#define LDSM4T(r, a) \
    asm volatile("ldmatrix.sync.aligned.m8n8.x4.trans.shared.b16 {%0,%1,%2,%3}, [%4];" \
                 : "=r"((r)[0]), "=r"((r)[1]), "=r"((r)[2]), "=r"((r)[3]) : "r"(a))

// Dekker split of 4 floats into bf16x2 hi pairs / lo pairs (memory order x,y / z,w)
__device__ __forceinline__ void bf16_split_pack(float4 v, uint32_t& h01, uint32_t& h23,
                                                uint32_t& l01, uint32_t& l23) {
    asm("cvt.rn.bf16x2.f32 %0, %1, %2;" : "=r"(h01) : "f"(v.y), "f"(v.x));
    asm("cvt.rn.bf16x2.f32 %0, %1, %2;" : "=r"(h23) : "f"(v.w), "f"(v.z));
    float hx = __uint_as_float(h01 << 16);
    float hy = __uint_as_float(h01 & 0xFFFF0000u);
    float hz = __uint_as_float(h23 << 16);
    float hw = __uint_as_float(h23 & 0xFFFF0000u);
    asm("cvt.rn.bf16x2.f32 %0, %1, %2;" : "=r"(l01) : "f"(v.y - hy), "f"(v.x - hx));
    asm("cvt.rn.bf16x2.f32 %0, %1, %2;" : "=r"(l23) : "f"(v.w - hw), "f"(v.z - hz));
}

// Row-major [row][8 words(16 b16)] tile, 32B rows, 16B-chunk xor swizzle.
__device__ __forceinline__ int tile_word(int row, int col) {
    return row * 8 + (col ^ (((row >> 2) & 1) << 2));
}

// ---------------------------------------------------------------------------
// QK: E tile [128 x 256] = Q[128 x 1024] @ K[256 x 1024]^T, 3-term bf16 split.
// 512 threads, warp grid 4x4, warp tile 32x64. BK=16. ldmatrix feeds.
// smem words: AH[2][1024], AL[2][1024], BH[2][2048], BL[2][2048] = 48KB.
// ---------------------------------------------------------------------------
#define QK_SMEM 49152

__global__ __launch_bounds__(512, 1) void qk_kernel(const float* __restrict__ Q,
                                                    const float* __restrict__ Km,
                                                    float* __restrict__ E)
{
    extern __shared__ uint32_t dsm[];
    const uint32_t sb = smem_u32(dsm);

    const int tid = threadIdx.x, wid = tid >> 5, lane = tid & 31;
    const int gid = lane >> 2, tig = lane & 3;
    const int wm = (wid >> 2) * 32, wn = (wid & 3) * 64;
    const int row0 = blockIdx.y * 128, col0 = blockIdx.x * 256;

    const float* Qb = Q  + (size_t)blockIdx.z * TQ * DIM;
    const float* Kb = Km + (size_t)blockIdx.z * TK * DIM;
    float*       Eb = E  + (size_t)blockIdx.z * TQ * TK;

    // ldmatrix lane address pieces
    const int row_l = (lane & 7) + ((lane >> 3) & 1) * 8;  // 0..15
    const int chnk  = (lane >> 4) & 1;                     // 16B chunk select

    uint32_t aoff[2], boff[4];
    #pragma unroll
    for (int mi = 0; mi < 2; mi++) {
        int m = wm + mi * 16 + row_l;
        aoff[mi] = (uint32_t)(m * 32 + (((chnk << 2) ^ (((m >> 2) & 1) << 2)) << 2));
    }
    #pragma unroll
    for (int g = 0; g < 4; g++) {
        int n = wn + g * 16 + row_l;
        boff[g] = (uint32_t)(n * 32 + (((chnk << 2) ^ (((n >> 2) & 1) << 2)) << 2));
    }

    // loader mapping
    const int lr  = tid >> 2;           // 0..127
    const int lk2 = (tid & 3) * 2;      // word col 0,2,4,6
    const int lkc = (tid & 3) * 4;      // k float offset

    float acc[2][8][4];
    #pragma unroll
    for (int i = 0; i < 2; i++)
        #pragma unroll
        for (int j = 0; j < 8; j++)
            #pragma unroll
            for (int c = 0; c < 4; c++) acc[i][j][c] = 0.0f;

    const int NIT = DIM / 16;  // 64
    float4 av, bv0, bv1;

    const int wa  = tile_word(lr, lk2);
    const int wb0 = wa;                 // same formula, row lr
    const int wb1 = wb0 + 128 * 8;      // row lr+128 (swizzle bit unchanged)

    av  = *reinterpret_cast<const float4*>(&Qb[(size_t)(row0 + lr) * DIM + lkc]);
    bv0 = *reinterpret_cast<const float4*>(&Kb[(size_t)(col0 + lr) * DIM + lkc]);
    bv1 = *reinterpret_cast<const float4*>(&Kb[(size_t)(col0 + 128 + lr) * DIM + lkc]);
    {
        uint32_t h01, h23, l01, l23;
        uint32_t* AHp = dsm;            // buf 0
        uint32_t* ALp = dsm + 2048;
        uint32_t* BHp = dsm + 4096;
        uint32_t* BLp = dsm + 8192;
        bf16_split_pack(av, h01, h23, l01, l23);
        *reinterpret_cast<uint2*>(AHp + wa) = make_uint2(h01, h23);
        *reinterpret_cast<uint2*>(ALp + wa) = make_uint2(l01, l23);
        bf16_split_pack(bv0, h01, h23, l01, l23);
        *reinterpret_cast<uint2*>(BHp + wb0) = make_uint2(h01, h23);
        *reinterpret_cast<uint2*>(BLp + wb0) = make_uint2(l01, l23);
        bf16_split_pack(bv1, h01, h23, l01, l23);
        *reinterpret_cast<uint2*>(BHp + wb1) = make_uint2(h01, h23);
        *reinterpret_cast<uint2*>(BLp + wb1) = make_uint2(l01, l23);
    }
    __syncthreads();

    int buf = 0;
    for (int it = 0; it < NIT; it++) {
        if (it + 1 < NIT) {
            int k0 = (it + 1) * 16;
            av  = *reinterpret_cast<const float4*>(&Qb[(size_t)(row0 + lr) * DIM + k0 + lkc]);
            bv0 = *reinterpret_cast<const float4*>(&Kb[(size_t)(col0 + lr) * DIM + k0 + lkc]);
            bv1 = *reinterpret_cast<const float4*>(&Kb[(size_t)(col0 + 128 + lr) * DIM + k0 + lkc]);
        }

        const uint32_t AHb = sb + buf * 4096;
        const uint32_t ALb = sb + 8192  + buf * 4096;
        const uint32_t BHb = sb + 16384 + buf * 8192;
        const uint32_t BLb = sb + 32768 + buf * 8192;

        uint32_t aH[2][4], aL[2][4];
        LDSM4(aH[0], AHb + aoff[0]);
        LDSM4(aH[1], AHb + aoff[1]);
        LDSM4(aL[0], ALb + aoff[0]);
        LDSM4(aL[1], ALb + aoff[1]);

        #pragma unroll
        for (int g = 0; g < 4; g++) {
            uint32_t bh[4], bl[4];
            LDSM4(bh, BHb + boff[g]);
            LDSM4(bl, BLb + boff[g]);
            // even ni: regs {0,2}; odd ni: {1,3}
            uint32_t be[2] = {bh[0], bh[2]}, bo[2] = {bh[1], bh[3]};
            uint32_t le[2] = {bl[0], bl[2]}, lo_[2] = {bl[1], bl[3]};
            #pragma unroll
            for (int mi = 0; mi < 2; mi++) {
                mma_bf16(acc[mi][2 * g],     aH[mi], be);
                mma_bf16(acc[mi][2 * g],     aH[mi], le);
                mma_bf16(acc[mi][2 * g],     aL[mi], be);
                mma_bf16(acc[mi][2 * g + 1], aH[mi], bo);
                mma_bf16(acc[mi][2 * g + 1], aH[mi], lo_);
                mma_bf16(acc[mi][2 * g + 1], aL[mi], bo);
            }
        }

        if (it + 1 < NIT) {
            uint32_t h01, h23, l01, l23;
            uint32_t* AHp = dsm + (buf ^ 1) * 1024;
            uint32_t* ALp = dsm + 2048 + (buf ^ 1) * 1024;
            uint32_t* BHp = dsm + 4096 + (buf ^ 1) * 2048;
            uint32_t* BLp = dsm + 8192 + (buf ^ 1) * 2048;
            bf16_split_pack(av, h01, h23, l01, l23);
            *reinterpret_cast<uint2*>(AHp + wa) = make_uint2(h01, h23);
            *reinterpret_cast<uint2*>(ALp + wa) = make_uint2(l01, l23);
            bf16_split_pack(bv0, h01, h23, l01, l23);
            *reinterpret_cast<uint2*>(BHp + wb0) = make_uint2(h01, h23);
            *reinterpret_cast<uint2*>(BLp + wb0) = make_uint2(l01, l23);
            bf16_split_pack(bv1, h01, h23, l01, l23);
            *reinterpret_cast<uint2*>(BHp + wb1) = make_uint2(h01, h23);
            *reinterpret_cast<uint2*>(BLp + wb1) = make_uint2(l01, l23);
            __syncthreads();
            buf ^= 1;
        }
    }

    #pragma unroll
    for (int mi = 0; mi < 2; mi++) {
        #pragma unroll
        for (int ni = 0; ni < 8; ni++) {
            int r = row0 + wm + mi * 16 + gid;
            int c = col0 + wn + ni * 8 + 2 * tig;
            *reinterpret_cast<float2*>(&Eb[(size_t)r * TK + c]) =
                make_float2(acc[mi][ni][0], acc[mi][ni][1]);
            *reinterpret_cast<float2*>(&Eb[(size_t)(r + 8) * TK + c]) =
                make_float2(acc[mi][ni][2], acc[mi][ni][3]);
        }
    }
}

// ---------------------------------------------------------------------------
// Softmax: read E f32 row, write P as f16 Dekker split (Phi + Plo).
// ---------------------------------------------------------------------------
__global__ __launch_bounds__(256) void softmax_split_kernel(const float* __restrict__ E,
                                                            __half* __restrict__ Phi,
                                                            __half* __restrict__ Plo)
{
    const float4* row = reinterpret_cast<const float4*>(E + (size_t)blockIdx.x * TK);
    const int t = threadIdx.x;

    float4 v0 = row[t];
    float4 v1 = row[t + 256];

    float m = fmaxf(fmaxf(fmaxf(v0.x, v0.y), fmaxf(v0.z, v0.w)),
                    fmaxf(fmaxf(v1.x, v1.y), fmaxf(v1.z, v1.w)));

    __shared__ float red[8];
    #pragma unroll
    for (int o = 16; o > 0; o >>= 1) m = fmaxf(m, __shfl_xor_sync(0xFFFFFFFFu, m, o));
    if ((t & 31) == 0) red[t >> 5] = m;
    __syncthreads();
    m = red[0];
    #pragma unroll
    for (int w = 1; w < 8; w++) m = fmaxf(m, red[w]);

    float4 e0, e1;
    e0.x = __expf(v0.x - m); e0.y = __expf(v0.y - m);
    e0.z = __expf(v0.z - m); e0.w = __expf(v0.w - m);
    e1.x = __expf(v1.x - m); e1.y = __expf(v1.y - m);
    e1.z = __expf(v1.z - m); e1.w = __expf(v1.w - m);

    float s = (e0.x + e0.y + e0.z + e0.w) + (e1.x + e1.y + e1.z + e1.w);
    #pragma unroll
    for (int o = 16; o > 0; o >>= 1) s += __shfl_xor_sync(0xFFFFFFFFu, s, o);
    __syncthreads();
    if ((t & 31) == 0) red[t >> 5] = s;
    __syncthreads();
    s = 0.0f;
    #pragma unroll
    for (int w = 0; w < 8; w++) s += red[w];

    float inv = 1.0f / s;
    e0.x *= inv; e0.y *= inv; e0.z *= inv; e0.w *= inv;
    e1.x *= inv; e1.y *= inv; e1.z *= inv; e1.w *= inv;

    __half* ph = Phi + (size_t)blockIdx.x * TK;
    __half* pl = Plo + (size_t)blockIdx.x * TK;

    #pragma unroll
    for (int part = 0; part < 2; part++) {
        float4 e = part ? e1 : e0;
        int idx = part ? (1024 + 4 * t) : (4 * t);
        __half2 h0 = __floats2half2_rn(e.x, e.y);
        __half2 h1 = __floats2half2_rn(e.z, e.w);
        float2 f0 = __half22float2(h0), f1 = __half22float2(h1);
        __half2 l0 = __floats2half2_rn(e.x - f0.x, e.y - f0.y);
        __half2 l1 = __floats2half2_rn(e.z - f1.x, e.w - f1.y);
        uint2 H, L;
        H.x = *reinterpret_cast<uint32_t*>(&h0); H.y = *reinterpret_cast<uint32_t*>(&h1);
        L.x = *reinterpret_cast<uint32_t*>(&l0); L.y = *reinterpret_cast<uint32_t*>(&l1);
        *reinterpret_cast<uint2*>(&ph[idx]) = H;
        *reinterpret_cast<uint2*>(&pl[idx]) = L;
    }
}

// ---------------------------------------------------------------------------
// PV: out tile [128 x 256] = P[128 x 2048] @ V[2048 x 256], f16 2-term
// (Phi*V + Plo*V), A via ldmatrix, B (V, [k][d] layout) via ldmatrix.trans.
// smem words: PHI[2][1024], PLO[2][1024], VT[2][2048] = 32KB.
// ---------------------------------------------------------------------------
#define PV_SMEM 32768

__global__ __launch_bounds__(512, 1) void pv_kernel(const __half* __restrict__ Phi,
                                                    const __half* __restrict__ Plo,
                                                    const float* __restrict__ V,
                                                    float* __restrict__ O)
{
    extern __shared__ uint32_t dsm[];
    const uint32_t sb = smem_u32(dsm);

    const int tid = threadIdx.x, wid = tid >> 5, lane = tid & 31;
    const int gid = lane >> 2, tig = lane & 3;
    const int wm = (wid >> 2) * 32, wn = (wid & 3) * 64;
    const int row0 = blockIdx.y * 128, col0 = blockIdx.x * 256;

    const __half* PhB = Phi + (size_t)blockIdx.z * TQ * TK;
    const __half* PlB = Plo + (size_t)blockIdx.z * TQ * TK;
    const float*  Vb  = V   + (size_t)blockIdx.z * TK * DIM;
    float*        Ob  = O   + (size_t)blockIdx.z * TQ * DIM;

    const int row_l = (lane & 7) + ((lane >> 3) & 1) * 8;
    const int chnk  = (lane >> 4) & 1;

    uint32_t aoff[2], boff[4];
    #pragma unroll
    for (int mi = 0; mi < 2; mi++) {
        int m = wm + mi * 16 + row_l;
        aoff[mi] = (uint32_t)(m * 32 + (((chnk << 2) ^ (((m >> 2) & 1) << 2)) << 2));
    }
    // B: tile [16 k][256 d] f16, 512B rows, chunk (16B=8 d) xor-swizzled by (k&7)
    {
        const int k_row = row_l;         // 0..15
        const int nadd  = chnk;          // +8 d
        #pragma unroll
        for (int g = 0; g < 4; g++) {
            int nch = ((wn + g * 16) >> 3) + nadd;
            int cl  = (nch & ~7) | ((nch ^ (k_row & 7)) & 7);
            boff[g] = (uint32_t)(k_row * 512 + cl * 16);
        }
    }

    // loaders
    const int lr  = tid >> 2;            // P rows 0..127
    const int lk2 = (tid & 3) * 2;
    const int wa  = tile_word(lr, lk2);
    const int vkr = tid >> 6;            // V k-row 0..7 (two passes)
    const int vd4 = (tid & 63) * 4;      // d offset

    float acc[2][8][4];
    #pragma unroll
    for (int i = 0; i < 2; i++)
        #pragma unroll
        for (int j = 0; j < 8; j++)
            #pragma unroll
            for (int c = 0; c < 4; c++) acc[i][j][c] = 0.0f;

    const int NIT = TK / 16;  // 128
    uint2 hv, lv;
    float4 vv0, vv1;

    auto v_word = [&](int kr, int d4) {
        int c = d4 >> 3;
        int cs = c ^ (kr & 7);
        return kr * 128 + cs * 4 + ((d4 >> 1) & 3);
    };

    hv  = *reinterpret_cast<const uint2*>(&PhB[(size_t)(row0 + lr) * TK + (tid & 3) * 4]);
    lv  = *reinterpret_cast<const uint2*>(&PlB[(size_t)(row0 + lr) * TK + (tid & 3) * 4]);
    vv0 = *reinterpret_cast<const float4*>(&Vb[(size_t)vkr * DIM + col0 + vd4]);
    vv1 = *reinterpret_cast<const float4*>(&Vb[(size_t)(vkr + 8) * DIM + col0 + vd4]);
    {
        uint32_t* PHp = dsm;
        uint32_t* PLp = dsm + 2048;
        uint32_t* VTp = dsm + 4096;
        *reinterpret_cast<uint2*>(PHp + wa) = hv;
        *reinterpret_cast<uint2*>(PLp + wa) = lv;
        __half2 w0 = __floats2half2_rn(vv0.x, vv0.y), w1 = __floats2half2_rn(vv0.z, vv0.w);
        *reinterpret_cast<uint2*>(VTp + v_word(vkr, vd4)) =
            make_uint2(*reinterpret_cast<uint32_t*>(&w0), *reinterpret_cast<uint32_t*>(&w1));
        w0 = __floats2half2_rn(vv1.x, vv1.y); w1 = __floats2half2_rn(vv1.z, vv1.w);
        *reinterpret_cast<uint2*>(VTp + v_word(vkr + 8, vd4)) =
            make_uint2(*reinterpret_cast<uint32_t*>(&w0), *reinterpret_cast<uint32_t*>(&w1));
    }
    __syncthreads();

    int buf = 0;
    for (int it = 0; it < NIT; it++) {
        if (it + 1 < NIT) {
            int k0 = (it + 1) * 16;
            hv  = *reinterpret_cast<const uint2*>(&PhB[(size_t)(row0 + lr) * TK + k0 + (tid & 3) * 4]);
            lv  = *reinterpret_cast<const uint2*>(&PlB[(size_t)(row0 + lr) * TK + k0 + (tid & 3) * 4]);
            vv0 = *reinterpret_cast<const float4*>(&Vb[(size_t)(k0 + vkr) * DIM + col0 + vd4]);
            vv1 = *reinterpret_cast<const float4*>(&Vb[(size_t)(k0 + vkr + 8) * DIM + col0 + vd4]);
        }

        const uint32_t PHb = sb + buf * 4096;
        const uint32_t PLb = sb + 8192  + buf * 4096;
        const uint32_t VTb = sb + 16384 + buf * 8192;

        uint32_t pH[2][4], pL[2][4];
        LDSM4(pH[0], PHb + aoff[0]);
        LDSM4(pH[1], PHb + aoff[1]);
        LDSM4(pL[0], PLb + aoff[0]);
        LDSM4(pL[1], PLb + aoff[1]);

        #pragma unroll
        for (int g = 0; g < 4; g++) {
            uint32_t bt[4];
            LDSM4T(bt, VTb + boff[g]);
            // trans order: even ni {r0,r1}, odd ni {r2,r3}
            uint32_t be[2] = {bt[0], bt[1]}, bo[2] = {bt[2], bt[3]};
            #pragma unroll
            for (int mi = 0; mi < 2; mi++) {
                mma_f16(acc[mi][2 * g],     pH[mi], be);
                mma_f16(acc[mi][2 * g],     pL[mi], be);
                mma_f16(acc[mi][2 * g + 1], pH[mi], bo);
                mma_f16(acc[mi][2 * g + 1], pL[mi], bo);
            }
        }

        if (it + 1 < NIT) {
            uint32_t* PHp = dsm + (buf ^ 1) * 1024;
            uint32_t* PLp = dsm + 2048 + (buf ^ 1) * 1024;
            uint32_t* VTp = dsm + 4096 + (buf ^ 1) * 2048;
            *reinterpret_cast<uint2*>(PHp + wa) = hv;
            *reinterpret_cast<uint2*>(PLp + wa) = lv;
            __half2 w0 = __floats2half2_rn(vv0.x, vv0.y), w1 = __floats2half2_rn(vv0.z, vv0.w);
            *reinterpret_cast<uint2*>(VTp + v_word(vkr, vd4)) =
                make_uint2(*reinterpret_cast<uint32_t*>(&w0), *reinterpret_cast<uint32_t*>(&w1));
            w0 = __floats2half2_rn(vv1.x, vv1.y); w1 = __floats2half2_rn(vv1.z, vv1.w);
            *reinterpret_cast<uint2*>(VTp + v_word(vkr + 8, vd4)) =
                make_uint2(*reinterpret_cast<uint32_t*>(&w0), *reinterpret_cast<uint32_t*>(&w1));
            __syncthreads();
            buf ^= 1;
        }
    }

    #pragma unroll
    for (int mi = 0; mi < 2; mi++) {
        #pragma unroll
        for (int ni = 0; ni < 8; ni++) {
            int r = row0 + wm + mi * 16 + gid;
            int c = col0 + wn + ni * 8 + 2 * tig;
            *reinterpret_cast<float2*>(&Ob[(size_t)r * DIM + c]) =
                make_float2(acc[mi][ni][0], acc[mi][ni][1]);
            *reinterpret_cast<float2*>(&Ob[(size_t)(r + 8) * DIM + c]) =
                make_float2(acc[mi][ni][2], acc[mi][ni][3]);
        }
    }
}

// ---------------------------------------------------------------------------
extern "C" void kernel_launch(void* const* d_in, const int* in_sizes, int n_in,
                              void* d_out, int out_size)
{
    const float* q   = (const float*)d_in[0];
    const float* key = (const float*)d_in[1];
    float*       out = (float*)d_out;

    float* energy = nullptr;
    __half *phi = nullptr, *plo = nullptr;
    cudaGetSymbolAddress((void**)&energy, g_energy);
    cudaGetSymbolAddress((void**)&phi, g_phi);
    cudaGetSymbolAddress((void**)&plo, g_plo);

    cudaFuncSetAttribute(qk_kernel, cudaFuncAttributeMaxDynamicSharedMemorySize, QK_SMEM);
    cudaFuncSetAttribute(pv_kernel, cudaFuncAttributeMaxDynamicSharedMemorySize, PV_SMEM);

    dim3 g1(TK / 256, TQ / 128, BATCH);
    qk_kernel<<<g1, 512, QK_SMEM>>>(q, key, energy);

    softmax_split_kernel<<<BATCH * TQ, 256>>>(energy, phi, plo);

    dim3 g2(DIM / 256, TQ / 128, BATCH);
    pv_kernel<<<g2, 512, PV_SMEM>>>(phi, plo, key, out);
}

// round 6
// speedup vs baseline: 3.1120x; 1.0135x over previous
#include <cuda_runtime.h>
#include <cuda_fp16.h>
#include <cstdint>

static const int BATCH = 8;
static const int TQ    = 2048;
static const int TK    = 2048;
static const int DIM   = 1024;

// Scratch buffers
__device__ float    g_energy[(size_t)8 * 2048 * 2048];        // 128 MB
__device__ __half   g_phi[(size_t)8 * 2048 * 2048];           // 64 MB
__device__ __half   g_plo[(size_t)8 * 2048 * 2048];           // 64 MB
__device__ uint32_t g_qhi[(size_t)8 * 2048 * 1024 / 2];       // 32 MB (bf16x2)
__device__ uint32_t g_qlo[(size_t)8 * 2048 * 1024 / 2];
__device__ uint32_t g_khi[(size_t)8 * 2048 * 1024 / 2];
__device__ uint32_t g_klo[(size_t)8 * 2048 * 1024 / 2];
__device__ uint32_t g_vh [(size_t)8 * 2048 * 1024 / 2];       // f16x2 of K (V role)

// ---------------------------------------------------------------------------
__device__ __forceinline__ uint32_t smem_u32(const void* p) {
    uint32_t a;
    asm("{ .reg .u64 t; cvta.to.shared.u64 t, %1; cvt.u32.u64 %0, t; }" : "=r"(a) : "l"(p));
    return a;
}

__device__ __forceinline__ void mma_bf16(float* d, const uint32_t* a, const uint32_t* b) {
    asm volatile(
        "mma.sync.aligned.m16n8k16.row.col.f32.bf16.bf16.f32 "
        "{%0,%1,%2,%3}, {%4,%5,%6,%7}, {%8,%9}, {%0,%1,%2,%3};"
        : "+f"(d[0]), "+f"(d[1]), "+f"(d[2]), "+f"(d[3])
        : "r"(a[0]), "r"(a[1]), "r"(a[2]), "r"(a[3]), "r"(b[0]), "r"(b[1]));
}
__device__ __forceinline__ void mma_f16(float* d, const uint32_t* a, const uint32_t* b) {
    asm volatile(
        "mma.sync.aligned.m16n8k16.row.col.f32.f16.f16.f32 "
        "{%0,%1,%2,%3}, {%4,%5,%6,%7}, {%8,%9}, {%0,%1,%2,%3};"
        : "+f"(d[0]), "+f"(d[1]), "+f"(d[2]), "+f"(d[3])
        : "r"(a[0]), "r"(a[1]), "r"(a[2]), "r"(a[3]), "r"(b[0]), "r"(b[1]));
}

#define LDSM4(r, a) \
    asm volatile("ldmatrix.sync.aligned.m8n8.x4.shared.b16 {%0,%1,%2,%3}, [%4];" \
                 : "=r"((r)[0]), "=r"((r)[1]), "=r"((r)[2]), "=r"((r)[3]) : "r"(a))
#define LDSM4T(r, a) \
    asm volatile("ldmatrix.sync.aligned.m8n8.x4.trans.shared.b16 {%0,%1,%2,%3}, [%4];" \
                 : "=r"((r)[0]), "=r"((r)[1]), "=r"((r)[2]), "=r"((r)[3]) : "r"(a))

#define CP16(dst, src) \
    asm volatile("cp.async.cg.shared.global [%0], [%1], 16;" :: "r"(dst), "l"(src))
#define CP_COMMIT() asm volatile("cp.async.commit_group;")
#define CP_WAIT2()  asm volatile("cp.async.wait_group 2;")

// Dekker split of 4 floats into bf16x2 hi/lo pairs (memory order x,y / z,w)
__device__ __forceinline__ void bf16_split_pack(float4 v, uint32_t& h01, uint32_t& h23,
                                                uint32_t& l01, uint32_t& l23) {
    asm("cvt.rn.bf16x2.f32 %0, %1, %2;" : "=r"(h01) : "f"(v.y), "f"(v.x));
    asm("cvt.rn.bf16x2.f32 %0, %1, %2;" : "=r"(h23) : "f"(v.w), "f"(v.z));
    float hx = __uint_as_float(h01 << 16);
    float hy = __uint_as_float(h01 & 0xFFFF0000u);
    float hz = __uint_as_float(h23 << 16);
    float hw = __uint_as_float(h23 & 0xFFFF0000u);
    asm("cvt.rn.bf16x2.f32 %0, %1, %2;" : "=r"(l01) : "f"(v.y - hy), "f"(v.x - hx));
    asm("cvt.rn.bf16x2.f32 %0, %1, %2;" : "=r"(l23) : "f"(v.w - hw), "f"(v.z - hz));
}

// ---------------------------------------------------------------------------
// Pre-pass: element-wise splits
// ---------------------------------------------------------------------------
__global__ __launch_bounds__(256) void split_q_kernel(const float* __restrict__ Q,
                                                      uint32_t* __restrict__ qhi,
                                                      uint32_t* __restrict__ qlo)
{
    size_t i = (size_t)blockIdx.x * 256 + threadIdx.x;
    float4 v = reinterpret_cast<const float4*>(Q)[i];
    uint32_t h01, h23, l01, l23;
    bf16_split_pack(v, h01, h23, l01, l23);
    reinterpret_cast<uint2*>(qhi)[i] = make_uint2(h01, h23);
    reinterpret_cast<uint2*>(qlo)[i] = make_uint2(l01, l23);
}

__global__ __launch_bounds__(256) void split_k_kernel(const float* __restrict__ Km,
                                                      uint32_t* __restrict__ khi,
                                                      uint32_t* __restrict__ klo,
                                                      uint32_t* __restrict__ vh)
{
    size_t i = (size_t)blockIdx.x * 256 + threadIdx.x;
    float4 v = reinterpret_cast<const float4*>(Km)[i];
    uint32_t h01, h23, l01, l23;
    bf16_split_pack(v, h01, h23, l01, l23);
    reinterpret_cast<uint2*>(khi)[i] = make_uint2(h01, h23);
    reinterpret_cast<uint2*>(klo)[i] = make_uint2(l01, l23);
    __half2 w0 = __floats2half2_rn(v.x, v.y);
    __half2 w1 = __floats2half2_rn(v.z, v.w);
    reinterpret_cast<uint2*>(vh)[i] =
        make_uint2(*reinterpret_cast<uint32_t*>(&w0), *reinterpret_cast<uint32_t*>(&w1));
}

// ---------------------------------------------------------------------------
// QK: E tile [128x128] = Qsplit @ Ksplit^T (3-term bf16). 256 thr, 2 CTA/SM.
// 4-stage cp.async pipeline. Stage = AH(4K) AL(4K) BH(4K) BL(4K) = 16KB.
// ---------------------------------------------------------------------------
#define QK_STAGE 16384
#define QK_SMEM  (4 * QK_STAGE)

__global__ __launch_bounds__(256, 2) void qk_kernel(const uint16_t* __restrict__ Qhi,
                                                    const uint16_t* __restrict__ Qlo,
                                                    const uint16_t* __restrict__ Khi,
                                                    const uint16_t* __restrict__ Klo,
                                                    float* __restrict__ E)
{
    extern __shared__ uint32_t dsm[];
    const uint32_t sb = smem_u32(dsm);

    const int tid = threadIdx.x, wid = tid >> 5, lane = tid & 31;
    const int gid = lane >> 2, tig = lane & 3;
    const int wm = (wid >> 1) * 32, wn = (wid & 1) * 64;
    const int row0 = blockIdx.y * 128, col0 = blockIdx.x * 128;

    const size_t bo = (size_t)blockIdx.z * TQ * DIM;
    const uint16_t* gAh = Qhi + bo;
    const uint16_t* gAl = Qlo + bo;
    const uint16_t* gBh = Khi + bo;
    const uint16_t* gBl = Klo + bo;
    float* Eb = E + (size_t)blockIdx.z * TQ * TK;

    // cp.async loader: each thread 1 16B chunk per tile (128 rows x 2 chunks)
    const int lr = tid >> 1, lch = tid & 1;
    const uint32_t ldst = (uint32_t)(lr * 32 + ((lch ^ ((lr >> 2) & 1)) * 16));
    const uint16_t* srcAh = gAh + (size_t)(row0 + lr) * DIM + lch * 8;
    const uint16_t* srcAl = gAl + (size_t)(row0 + lr) * DIM + lch * 8;
    const uint16_t* srcBh = gBh + (size_t)(col0 + lr) * DIM + lch * 8;
    const uint16_t* srcBl = gBl + (size_t)(col0 + lr) * DIM + lch * 8;

    // ldmatrix offsets
    const int row_l = (lane & 7) + ((lane >> 3) & 1) * 8;
    const int chnk  = (lane >> 4) & 1;
    uint32_t aoff[2], boff[4];
    #pragma unroll
    for (int mi = 0; mi < 2; mi++) {
        int m = wm + mi * 16 + row_l;
        aoff[mi] = (uint32_t)(m * 32 + (((chnk << 2) ^ (((m >> 2) & 1) << 2)) << 2));
    }
    #pragma unroll
    for (int g = 0; g < 4; g++) {
        int n = wn + g * 16 + row_l;
        boff[g] = (uint32_t)(n * 32 + (((chnk << 2) ^ (((n >> 2) & 1) << 2)) << 2));
    }

    float acc[2][8][4];
    #pragma unroll
    for (int i = 0; i < 2; i++)
        #pragma unroll
        for (int j = 0; j < 8; j++)
            #pragma unroll
            for (int c = 0; c < 4; c++) acc[i][j][c] = 0.0f;

    const int NIT = DIM / 16;  // 64

    auto issue = [&](int it) {
        uint32_t d = sb + (it & 3) * QK_STAGE + ldst;
        size_t go = (size_t)it * 16;
        CP16(d,         srcAh + go);
        CP16(d + 4096,  srcAl + go);
        CP16(d + 8192,  srcBh + go);
        CP16(d + 12288, srcBl + go);
        CP_COMMIT();
    };

    issue(0); issue(1); issue(2);

    for (int it = 0; it < NIT; it++) {
        CP_WAIT2();
        __syncthreads();
        if (it + 3 < NIT) issue(it + 3);

        const uint32_t base = sb + (it & 3) * QK_STAGE;
        uint32_t aH[2][4], aL[2][4];
        LDSM4(aH[0], base + aoff[0]);
        LDSM4(aH[1], base + aoff[1]);
        LDSM4(aL[0], base + 4096 + aoff[0]);
        LDSM4(aL[1], base + 4096 + aoff[1]);

        #pragma unroll
        for (int g = 0; g < 4; g++) {
            uint32_t bh[4], bl[4];
            LDSM4(bh, base + 8192 + boff[g]);
            LDSM4(bl, base + 12288 + boff[g]);
            uint32_t be[2] = {bh[0], bh[2]}, bo_[2] = {bh[1], bh[3]};
            uint32_t le[2] = {bl[0], bl[2]}, lo_[2] = {bl[1], bl[3]};
            #pragma unroll
            for (int mi = 0; mi < 2; mi++) {
                mma_bf16(acc[mi][2 * g],     aH[mi], be);
                mma_bf16(acc[mi][2 * g],     aH[mi], le);
                mma_bf16(acc[mi][2 * g],     aL[mi], be);
                mma_bf16(acc[mi][2 * g + 1], aH[mi], bo_);
                mma_bf16(acc[mi][2 * g + 1], aH[mi], lo_);
                mma_bf16(acc[mi][2 * g + 1], aL[mi], bo_);
            }
        }
    }

    #pragma unroll
    for (int mi = 0; mi < 2; mi++) {
        #pragma unroll
        for (int ni = 0; ni < 8; ni++) {
            int r = row0 + wm + mi * 16 + gid;
            int c = col0 + wn + ni * 8 + 2 * tig;
            *reinterpret_cast<float2*>(&Eb[(size_t)r * TK + c]) =
                make_float2(acc[mi][ni][0], acc[mi][ni][1]);
            *reinterpret_cast<float2*>(&Eb[(size_t)(r + 8) * TK + c]) =
                make_float2(acc[mi][ni][2], acc[mi][ni][3]);
        }
    }
}

// ---------------------------------------------------------------------------
// Softmax: read E f32 row, write P as f16 Dekker split.
// ---------------------------------------------------------------------------
__global__ __launch_bounds__(256) void softmax_split_kernel(const float* __restrict__ E,
                                                            __half* __restrict__ Phi,
                                                            __half* __restrict__ Plo)
{
    const float4* row = reinterpret_cast<const float4*>(E + (size_t)blockIdx.x * TK);
    const int t = threadIdx.x;

    float4 v0 = row[t];
    float4 v1 = row[t + 256];

    float m = fmaxf(fmaxf(fmaxf(v0.x, v0.y), fmaxf(v0.z, v0.w)),
                    fmaxf(fmaxf(v1.x, v1.y), fmaxf(v1.z, v1.w)));

    __shared__ float red[8];
    #pragma unroll
    for (int o = 16; o > 0; o >>= 1) m = fmaxf(m, __shfl_xor_sync(0xFFFFFFFFu, m, o));
    if ((t & 31) == 0) red[t >> 5] = m;
    __syncthreads();
    m = red[0];
    #pragma unroll
    for (int w = 1; w < 8; w++) m = fmaxf(m, red[w]);

    float4 e0, e1;
    e0.x = __expf(v0.x - m); e0.y = __expf(v0.y - m);
    e0.z = __expf(v0.z - m); e0.w = __expf(v0.w - m);
    e1.x = __expf(v1.x - m); e1.y = __expf(v1.y - m);
    e1.z = __expf(v1.z - m); e1.w = __expf(v1.w - m);

    float s = (e0.x + e0.y + e0.z + e0.w) + (e1.x + e1.y + e1.z + e1.w);
    #pragma unroll
    for (int o = 16; o > 0; o >>= 1) s += __shfl_xor_sync(0xFFFFFFFFu, s, o);
    __syncthreads();
    if ((t & 31) == 0) red[t >> 5] = s;
    __syncthreads();
    s = 0.0f;
    #pragma unroll
    for (int w = 0; w < 8; w++) s += red[w];

    float inv = 1.0f / s;
    e0.x *= inv; e0.y *= inv; e0.z *= inv; e0.w *= inv;
    e1.x *= inv; e1.y *= inv; e1.z *= inv; e1.w *= inv;

    __half* ph = Phi + (size_t)blockIdx.x * TK;
    __half* pl = Plo + (size_t)blockIdx.x * TK;

    #pragma unroll
    for (int part = 0; part < 2; part++) {
        float4 e = part ? e1 : e0;
        int idx = part ? (1024 + 4 * t) : (4 * t);
        __half2 h0 = __floats2half2_rn(e.x, e.y);
        __half2 h1 = __floats2half2_rn(e.z, e.w);
        float2 f0 = __half22float2(h0), f1 = __half22float2(h1);
        __half2 l0 = __floats2half2_rn(e.x - f0.x, e.y - f0.y);
        __half2 l1 = __floats2half2_rn(e.z - f1.x, e.w - f1.y);
        uint2 H, L;
        H.x = *reinterpret_cast<uint32_t*>(&h0); H.y = *reinterpret_cast<uint32_t*>(&h1);
        L.x = *reinterpret_cast<uint32_t*>(&l0); L.y = *reinterpret_cast<uint32_t*>(&l1);
        *reinterpret_cast<uint2*>(&ph[idx]) = H;
        *reinterpret_cast<uint2*>(&pl[idx]) = L;
    }
}

// ---------------------------------------------------------------------------
// PV: O tile [128x128] = (Phi+Plo)[128x2048] @ Vf16[2048x128]. 256 thr, 2/SM.
// 4-stage cp.async pipeline. Stage = PH(4K) PL(4K) V(4K) = 12KB.
// ---------------------------------------------------------------------------
#define PV_STAGE 12288
#define PV_SMEM  (4 * PV_STAGE)

__global__ __launch_bounds__(256, 2) void pv_kernel(const uint16_t* __restrict__ Phi,
                                                    const uint16_t* __restrict__ Plo,
                                                    const uint16_t* __restrict__ Vh,
                                                    float* __restrict__ O)
{
    extern __shared__ uint32_t dsm[];
    const uint32_t sb = smem_u32(dsm);

    const int tid = threadIdx.x, wid = tid >> 5, lane = tid & 31;
    const int gid = lane >> 2, tig = lane & 3;
    const int wm = (wid >> 1) * 32, wn = (wid & 1) * 64;
    const int row0 = blockIdx.y * 128, col0 = blockIdx.x * 128;

    const uint16_t* PhB = Phi + (size_t)blockIdx.z * TQ * TK;
    const uint16_t* PlB = Plo + (size_t)blockIdx.z * TQ * TK;
    const uint16_t* VhB = Vh  + (size_t)blockIdx.z * TK * DIM;
    float*          Ob  = O   + (size_t)blockIdx.z * TQ * DIM;

    // P loader: 128 rows x 2 chunks
    const int lr = tid >> 1, lch = tid & 1;
    const uint32_t pdst = (uint32_t)(lr * 32 + ((lch ^ ((lr >> 2) & 1)) * 16));
    const uint16_t* srcPh = PhB + (size_t)(row0 + lr) * TK + lch * 8;
    const uint16_t* srcPl = PlB + (size_t)(row0 + lr) * TK + lch * 8;
    // V loader: 16 k-rows x 16 chunks (128 d)
    const int vr = tid >> 4, vc = tid & 15;
    const uint32_t vdst = (uint32_t)(vr * 256 + (((vc & 8) | ((vc ^ vr) & 7)) * 16));
    const uint16_t* srcV = VhB + (size_t)vr * DIM + col0 + vc * 8;

    // ldmatrix offsets
    const int row_l = (lane & 7) + ((lane >> 3) & 1) * 8;
    const int chnk  = (lane >> 4) & 1;
    uint32_t aoff[2], boff[4];
    #pragma unroll
    for (int mi = 0; mi < 2; mi++) {
        int m = wm + mi * 16 + row_l;
        aoff[mi] = (uint32_t)(m * 32 + (((chnk << 2) ^ (((m >> 2) & 1) << 2)) << 2));
    }
    #pragma unroll
    for (int g = 0; g < 4; g++) {
        int nch = ((wn + g * 16) >> 3) + chnk;
        int cl  = (nch & 8) | ((nch ^ (row_l & 7)) & 7);
        boff[g] = (uint32_t)(row_l * 256 + cl * 16);
    }

    float acc[2][8][4];
    #pragma unroll
    for (int i = 0; i < 2; i++)
        #pragma unroll
        for (int j = 0; j < 8; j++)
            #pragma unroll
            for (int c = 0; c < 4; c++) acc[i][j][c] = 0.0f;

    const int NIT = TK / 16;  // 128

    auto issue = [&](int it) {
        uint32_t base = sb + (it & 3) * PV_STAGE;
        size_t go = (size_t)it * 16;
        CP16(base + pdst,        srcPh + go);
        CP16(base + 4096 + pdst, srcPl + go);
        CP16(base + 8192 + vdst, srcV + go * DIM);
        CP_COMMIT();
    };

    issue(0); issue(1); issue(2);

    for (int it = 0; it < NIT; it++) {
        CP_WAIT2();
        __syncthreads();
        if (it + 3 < NIT) issue(it + 3);

        const uint32_t base = sb + (it & 3) * PV_STAGE;
        uint32_t pH[2][4], pL[2][4];
        LDSM4(pH[0], base + aoff[0]);
        LDSM4(pH[1], base + aoff[1]);
        LDSM4(pL[0], base + 4096 + aoff[0]);
        LDSM4(pL[1], base + 4096 + aoff[1]);

        #pragma unroll
        for (int g = 0; g < 4; g++) {
            uint32_t bt[4];
            LDSM4T(bt, base + 8192 + boff[g]);
            uint32_t be[2] = {bt[0], bt[1]}, bo_[2] = {bt[2], bt[3]};
            #pragma unroll
            for (int mi = 0; mi < 2; mi++) {
                mma_f16(acc[mi][2 * g],     pH[mi], be);
                mma_f16(acc[mi][2 * g],     pL[mi], be);
                mma_f16(acc[mi][2 * g + 1], pH[mi], bo_);
                mma_f16(acc[mi][2 * g + 1], pL[mi], bo_);
            }
        }
    }

    #pragma unroll
    for (int mi = 0; mi < 2; mi++) {
        #pragma unroll
        for (int ni = 0; ni < 8; ni++) {
            int r = row0 + wm + mi * 16 + gid;
            int c = col0 + wn + ni * 8 + 2 * tig;
            *reinterpret_cast<float2*>(&Ob[(size_t)r * DIM + c]) =
                make_float2(acc[mi][ni][0], acc[mi][ni][1]);
            *reinterpret_cast<float2*>(&Ob[(size_t)(r + 8) * DIM + c]) =
                make_float2(acc[mi][ni][2], acc[mi][ni][3]);
        }
    }
}

// ---------------------------------------------------------------------------
extern "C" void kernel_launch(void* const* d_in, const int* in_sizes, int n_in,
                              void* d_out, int out_size)
{
    const float* q   = (const float*)d_in[0];
    const float* key = (const float*)d_in[1];
    float*       out = (float*)d_out;

    float* energy = nullptr;
    __half *phi = nullptr, *plo = nullptr;
    uint32_t *qhi, *qlo, *khi, *klo, *vh;
    cudaGetSymbolAddress((void**)&energy, g_energy);
    cudaGetSymbolAddress((void**)&phi, g_phi);
    cudaGetSymbolAddress((void**)&plo, g_plo);
    cudaGetSymbolAddress((void**)&qhi, g_qhi);
    cudaGetSymbolAddress((void**)&qlo, g_qlo);
    cudaGetSymbolAddress((void**)&khi, g_khi);
    cudaGetSymbolAddress((void**)&klo, g_klo);
    cudaGetSymbolAddress((void**)&vh,  g_vh);

    cudaFuncSetAttribute(qk_kernel, cudaFuncAttributeMaxDynamicSharedMemorySize, QK_SMEM);
    cudaFuncSetAttribute(pv_kernel, cudaFuncAttributeMaxDynamicSharedMemorySize, PV_SMEM);

    const int nv4 = (int)((size_t)BATCH * TQ * DIM / 4 / 256);  // 16384 blocks
    split_q_kernel<<<nv4, 256>>>(q, qhi, qlo);
    split_k_kernel<<<nv4, 256>>>(key, khi, klo, vh);

    dim3 g1(TK / 128, TQ / 128, BATCH);
    qk_kernel<<<g1, 256, QK_SMEM>>>((const uint16_t*)qhi, (const uint16_t*)qlo,
                                    (const uint16_t*)khi, (const uint16_t*)klo, energy);

    softmax_split_kernel<<<BATCH * TQ, 256>>>(energy, phi, plo);

    dim3 g2(DIM / 128, TQ / 128, BATCH);
    pv_kernel<<<g2, 256, PV_SMEM>>>((const uint16_t*)phi, (const uint16_t*)plo,
                                    (const uint16_t*)vh, out);
}